// round 1
// baseline (speedup 1.0000x reference)
#include <cuda_runtime.h>

// HorizontalWidthTokenPyramid: x [N=32, C=256, S=32, H=16, W=16] f32
//   -> out [N, C, S, 31, 4] f32
// Per (n,c,s) slice (16x16):
//   for b in {16,8,4,2,1}: split H into b bins, z = mean_h + max_h  [b,16]
//   then pool W into 4 tokens: mean_w + max_w                       [b,4]
// Bins concatenated in order 16,8,4,2,1 -> 31 bins.
//
// Mapping: 4 threads per slice; thread q owns columns 4q..4q+3 (one output
// token) -> each row read is a single float4; all H-pyramid folding is
// in-register (sum/max pairs nest across levels). Results staged in smem,
// then written fully coalesced.

namespace {

constexpr int THREADS          = 256;
constexpr int SLICES_PER_BLOCK = 64;        // THREADS / 4
constexpr int OUT_PER_SLICE    = 31 * 4;    // 124
constexpr int SLICE_FLOATS     = 256;       // 16*16

__device__ __forceinline__ float max4(float a, float b, float c, float d) {
    return fmaxf(fmaxf(a, b), fmaxf(c, d));
}
__device__ __forceinline__ float sum4(float a, float b, float c, float d) {
    return (a + b) + (c + d);
}

__global__ __launch_bounds__(THREADS, 2)
void hwtp_kernel(const float4* __restrict__ x4, float* __restrict__ out) {
    __shared__ float sm[SLICES_PER_BLOCK * OUT_PER_SLICE];  // 31744 B

    const int tid = threadIdx.x;
    const int sl  = tid >> 2;   // local slice 0..63
    const int q   = tid & 3;    // width token 0..3 (owns cols 4q..4q+3)

    const long slice = (long)blockIdx.x * SLICES_PER_BLOCK + sl;
    // slice = 64 float4; each row = 4 float4; this thread reads float4 #q of each row
    const float4* p = x4 + slice * (SLICE_FLOATS / 4) + q;

    float* o = &sm[sl * OUT_PER_SLICE + q];   // write o[bin*4]

    // Per-column running (sum, max) at level b=8 (pairs of rows)
    float s8[8][4], m8[8][4];

    #pragma unroll
    for (int r = 0; r < 16; ++r) {
        const float4 v = p[r * 4];
        const float a = v.x, b = v.y, c = v.z, d = v.w;

        // level b=16 (bin size 1): z = v + v = 2v
        //   token = mean(z) + max(z) = 0.5*sum4(v) + 2*max4(v)
        o[r * 4] = 0.5f * sum4(a, b, c, d) + 2.0f * max4(a, b, c, d);

        const int i = r >> 1;
        if ((r & 1) == 0) {
            s8[i][0] = a; s8[i][1] = b; s8[i][2] = c; s8[i][3] = d;
            m8[i][0] = a; m8[i][1] = b; m8[i][2] = c; m8[i][3] = d;
        } else {
            s8[i][0] += a; s8[i][1] += b; s8[i][2] += c; s8[i][3] += d;
            m8[i][0] = fmaxf(m8[i][0], a);
            m8[i][1] = fmaxf(m8[i][1], b);
            m8[i][2] = fmaxf(m8[i][2], c);
            m8[i][3] = fmaxf(m8[i][3], d);
        }
    }

    // level b=8 (bin size 2): bins 16..23, mean = sum/2
    #pragma unroll
    for (int i = 0; i < 8; ++i) {
        const float z0 = 0.5f * s8[i][0] + m8[i][0];
        const float z1 = 0.5f * s8[i][1] + m8[i][1];
        const float z2 = 0.5f * s8[i][2] + m8[i][2];
        const float z3 = 0.5f * s8[i][3] + m8[i][3];
        o[(16 + i) * 4] = 0.25f * sum4(z0, z1, z2, z3) + max4(z0, z1, z2, z3);
    }

    // fold to level b=4
    float s4v[4][4], m4v[4][4];
    #pragma unroll
    for (int i = 0; i < 4; ++i)
        #pragma unroll
        for (int c = 0; c < 4; ++c) {
            s4v[i][c] = s8[2 * i][c] + s8[2 * i + 1][c];
            m4v[i][c] = fmaxf(m8[2 * i][c], m8[2 * i + 1][c]);
        }

    // level b=4 (bin size 4): bins 24..27, mean = sum/4
    #pragma unroll
    for (int i = 0; i < 4; ++i) {
        const float z0 = 0.25f * s4v[i][0] + m4v[i][0];
        const float z1 = 0.25f * s4v[i][1] + m4v[i][1];
        const float z2 = 0.25f * s4v[i][2] + m4v[i][2];
        const float z3 = 0.25f * s4v[i][3] + m4v[i][3];
        o[(24 + i) * 4] = 0.25f * sum4(z0, z1, z2, z3) + max4(z0, z1, z2, z3);
    }

    // fold to level b=2
    float s2v[2][4], m2v[2][4];
    #pragma unroll
    for (int i = 0; i < 2; ++i)
        #pragma unroll
        for (int c = 0; c < 4; ++c) {
            s2v[i][c] = s4v[2 * i][c] + s4v[2 * i + 1][c];
            m2v[i][c] = fmaxf(m4v[2 * i][c], m4v[2 * i + 1][c]);
        }

    // level b=2 (bin size 8): bins 28..29, mean = sum/8
    #pragma unroll
    for (int i = 0; i < 2; ++i) {
        const float z0 = 0.125f * s2v[i][0] + m2v[i][0];
        const float z1 = 0.125f * s2v[i][1] + m2v[i][1];
        const float z2 = 0.125f * s2v[i][2] + m2v[i][2];
        const float z3 = 0.125f * s2v[i][3] + m2v[i][3];
        o[(28 + i) * 4] = 0.25f * sum4(z0, z1, z2, z3) + max4(z0, z1, z2, z3);
    }

    // level b=1 (bin size 16): bin 30, mean = sum/16
    {
        float s1v[4], m1v[4];
        #pragma unroll
        for (int c = 0; c < 4; ++c) {
            s1v[c] = s2v[0][c] + s2v[1][c];
            m1v[c] = fmaxf(m2v[0][c], m2v[1][c]);
        }
        const float z0 = 0.0625f * s1v[0] + m1v[0];
        const float z1 = 0.0625f * s1v[1] + m1v[1];
        const float z2 = 0.0625f * s1v[2] + m1v[2];
        const float z3 = 0.0625f * s1v[3] + m1v[3];
        o[30 * 4] = 0.25f * sum4(z0, z1, z2, z3) + max4(z0, z1, z2, z3);
    }

    __syncthreads();

    // Coalesced flush: 64 slices * 124 floats = 7936 contiguous floats
    float* ob = out + (long)blockIdx.x * (SLICES_PER_BLOCK * OUT_PER_SLICE);
    constexpr int ITERS = (SLICES_PER_BLOCK * OUT_PER_SLICE) / THREADS;  // 31
    #pragma unroll
    for (int i = 0; i < ITERS; ++i)
        ob[i * THREADS + tid] = sm[i * THREADS + tid];
}

}  // namespace

extern "C" void kernel_launch(void* const* d_in, const int* in_sizes, int n_in,
                              void* d_out, int out_size) {
    const float* x = (const float*)d_in[0];
    float* out = (float*)d_out;

    const long total_floats = (long)in_sizes[0];     // 67,108,864
    const long slices = total_floats / SLICE_FLOATS; // 262,144
    const int blocks = (int)(slices / SLICES_PER_BLOCK); // 4096

    hwtp_kernel<<<blocks, THREADS>>>(
        reinterpret_cast<const float4*>(x), out);
}

// round 2
// speedup vs baseline: 1.2464x; 1.2464x over previous
#include <cuda_runtime.h>

// HorizontalWidthTokenPyramid: x [32, 256, 32, 16, 16] f32
//   -> out [N*C*S, 31, 4] f32
// Per (n,c,s) 16x16 slice: for b in {16,8,4,2,1}: bin H into b bins
// (mean+max), then pool W 16->4 tokens (mean+max). Bins concat -> 31.
//
// Mapping: 4 threads/slice, thread q owns cols 4q..4q+3 (one token) ->
// one float4 load per row. Pyramid folded PROGRESSIVELY (emit each bin as
// its row-span completes) so only one accumulator per level stays live:
// ~32 floats of state instead of 64 -> fewer regs -> 4 blocks/SM.

namespace {

constexpr int THREADS          = 256;
constexpr int SLICES_PER_BLOCK = 64;        // THREADS / 4
constexpr int OUT_PER_SLICE    = 31 * 4;    // 124
constexpr int SLICE_FLOATS     = 256;       // 16*16

__device__ __forceinline__ float max4(float a, float b, float c, float d) {
    return fmaxf(fmaxf(a, b), fmaxf(c, d));
}
__device__ __forceinline__ float sum4(float a, float b, float c, float d) {
    return (a + b) + (c + d);
}
// token output for a bin: z_c = inv*sum_c + max_c ; out = 0.25*sum(z) + max(z)
__device__ __forceinline__ float token(const float s[4], const float m[4], float inv) {
    const float z0 = inv * s[0] + m[0];
    const float z1 = inv * s[1] + m[1];
    const float z2 = inv * s[2] + m[2];
    const float z3 = inv * s[3] + m[3];
    return 0.25f * sum4(z0, z1, z2, z3) + max4(z0, z1, z2, z3);
}

__global__ __launch_bounds__(THREADS, 4)
void hwtp_kernel(const float4* __restrict__ x4, float* __restrict__ out) {
    __shared__ float sm[SLICES_PER_BLOCK * OUT_PER_SLICE];  // 31744 B

    const int tid = threadIdx.x;
    const int sl  = tid >> 2;   // local slice 0..63
    const int q   = tid & 3;    // width token 0..3

    const long slice = (long)blockIdx.x * SLICES_PER_BLOCK + sl;
    const float4* p = x4 + slice * (SLICE_FLOATS / 4) + q;

    float* o = &sm[sl * OUT_PER_SLICE + q];   // write o[bin*4]

    // running accumulators (sum,max per column) per pyramid level
    float s4v[4], m4v[4];   // level b=4  (4 rows)
    float s2v[4], m2v[4];   // level b=2  (8 rows)
    float s1v[4], m1v[4];   // level b=1  (16 rows)

    #pragma unroll
    for (int i = 0; i < 8; ++i) {           // row pair i = rows 2i, 2i+1
        const float4 v0 = p[(2 * i) * 4];
        const float4 v1 = p[(2 * i + 1) * 4];

        // level b=16 (bin size 1): mean+max over 1 row = 2*row
        o[(2 * i) * 4]     = 0.5f * sum4(v0.x, v0.y, v0.z, v0.w)
                           + 2.0f * max4(v0.x, v0.y, v0.z, v0.w);
        o[(2 * i + 1) * 4] = 0.5f * sum4(v1.x, v1.y, v1.z, v1.w)
                           + 2.0f * max4(v1.x, v1.y, v1.z, v1.w);

        // pair (level b=8 bin)
        float ps[4] = { v0.x + v1.x, v0.y + v1.y, v0.z + v1.z, v0.w + v1.w };
        float pm[4] = { fmaxf(v0.x, v1.x), fmaxf(v0.y, v1.y),
                        fmaxf(v0.z, v1.z), fmaxf(v0.w, v1.w) };
        o[(16 + i) * 4] = token(ps, pm, 0.5f);

        // fold pair into level b=4
        if ((i & 1) == 0) {
            #pragma unroll
            for (int c = 0; c < 4; ++c) { s4v[c] = ps[c]; m4v[c] = pm[c]; }
        } else {
            #pragma unroll
            for (int c = 0; c < 4; ++c) {
                s4v[c] += ps[c]; m4v[c] = fmaxf(m4v[c], pm[c]);
            }
            const int j = i >> 1;           // completed level-4 bin
            o[(24 + j) * 4] = token(s4v, m4v, 0.25f);

            // fold level-4 bin into level b=2
            if ((j & 1) == 0) {
                #pragma unroll
                for (int c = 0; c < 4; ++c) { s2v[c] = s4v[c]; m2v[c] = m4v[c]; }
            } else {
                #pragma unroll
                for (int c = 0; c < 4; ++c) {
                    s2v[c] += s4v[c]; m2v[c] = fmaxf(m2v[c], m4v[c]);
                }
                const int t = j >> 1;       // completed level-2 bin
                o[(28 + t) * 4] = token(s2v, m2v, 0.125f);

                // fold level-2 bin into level b=1
                if (t == 0) {
                    #pragma unroll
                    for (int c = 0; c < 4; ++c) { s1v[c] = s2v[c]; m1v[c] = m2v[c]; }
                } else {
                    #pragma unroll
                    for (int c = 0; c < 4; ++c) {
                        s1v[c] += s2v[c]; m1v[c] = fmaxf(m1v[c], m2v[c]);
                    }
                    o[30 * 4] = token(s1v, m1v, 0.0625f);
                }
            }
        }
    }

    __syncthreads();

    // Coalesced flush: 64 slices * 124 floats = 7936 contiguous floats
    float* ob = out + (long)blockIdx.x * (SLICES_PER_BLOCK * OUT_PER_SLICE);
    constexpr int ITERS = (SLICES_PER_BLOCK * OUT_PER_SLICE) / THREADS;  // 31
    #pragma unroll
    for (int i = 0; i < ITERS; ++i)
        ob[i * THREADS + tid] = sm[i * THREADS + tid];
}

}  // namespace

extern "C" void kernel_launch(void* const* d_in, const int* in_sizes, int n_in,
                              void* d_out, int out_size) {
    const float* x = (const float*)d_in[0];
    float* out = (float*)d_out;

    const long total_floats = (long)in_sizes[0];       // 67,108,864
    const long slices = total_floats / SLICE_FLOATS;   // 262,144
    const int blocks = (int)(slices / SLICES_PER_BLOCK); // 4096

    hwtp_kernel<<<blocks, THREADS>>>(reinterpret_cast<const float4*>(x), out);
}